// round 3
// baseline (speedup 1.0000x reference)
#include <cuda_runtime.h>
#include <cstddef>

// Problem constants
#define B_  8
#define T_  2048
#define D_  256
#define DK_ 64
#define NHEAD_ 4

// Fused attention kernel tiling
#define R_   16      // query rows per CTA
#define ST_  128     // key/value tile along s
#define TH_  256     // threads per CTA

// Scratch for projected q/k/v  (8*2048*64 fp32 = 4 MB each)
__device__ float g_qs[B_ * T_ * DK_];
__device__ float g_ks[B_ * T_ * DK_];
__device__ float g_vs[B_ * T_ * DK_];

// ---------------------------------------------------------------------------
// Kernel 1: projections  qs = q@Wq, ks = k@Wk, vs = v@Wv
// grid = (512, 3), block = 256.  Each block: 32 rows x 64 cols of one proj.
// ---------------------------------------------------------------------------
__global__ void proj_kernel(const float* __restrict__ q,
                            const float* __restrict__ k,
                            const float* __restrict__ v,
                            const float* __restrict__ Wq,
                            const float* __restrict__ Wk,
                            const float* __restrict__ Wv) {
    __shared__ float xs[32 * 256];

    const float* x;
    const float* W;
    float* dst;
    if (blockIdx.y == 0)      { x = q; W = Wq; dst = g_qs; }
    else if (blockIdx.y == 1) { x = k; W = Wk; dst = g_ks; }
    else                      { x = v; W = Wv; dst = g_vs; }

    const int row0 = blockIdx.x * 32;
    const int tid  = threadIdx.x;

    // load 32 input rows (32*256 floats) as float4
    {
        const float4* src4 = reinterpret_cast<const float4*>(x + (size_t)row0 * D_);
        float4* xs4 = reinterpret_cast<float4*>(xs);
        #pragma unroll
        for (int i = tid; i < 32 * 256 / 4; i += TH_) xs4[i] = src4[i];
    }
    __syncthreads();

    // thread tile: 2 rows x 4 cols
    const int jg = tid & 15;          // 16 col groups
    const int rg = tid >> 4;          // 16 row groups
    const int j0 = jg * 4;
    const int r0 = rg * 2;

    float acc0[4] = {0.f, 0.f, 0.f, 0.f};
    float acc1[4] = {0.f, 0.f, 0.f, 0.f};

    for (int i = 0; i < D_; i += 4) {
        float4 xa = *reinterpret_cast<const float4*>(&xs[r0 * 256 + i]);
        float4 xb = *reinterpret_cast<const float4*>(&xs[(r0 + 1) * 256 + i]);
        const float xav[4] = {xa.x, xa.y, xa.z, xa.w};
        const float xbv[4] = {xb.x, xb.y, xb.z, xb.w};
        #pragma unroll
        for (int ii = 0; ii < 4; ii++) {
            float4 w = *reinterpret_cast<const float4*>(&W[(size_t)(i + ii) * DK_ + j0]);
            acc0[0] += xav[ii] * w.x; acc0[1] += xav[ii] * w.y;
            acc0[2] += xav[ii] * w.z; acc0[3] += xav[ii] * w.w;
            acc1[0] += xbv[ii] * w.x; acc1[1] += xbv[ii] * w.y;
            acc1[2] += xbv[ii] * w.z; acc1[3] += xbv[ii] * w.w;
        }
    }

    float4* o0 = reinterpret_cast<float4*>(&dst[(size_t)(row0 + r0) * DK_ + j0]);
    float4* o1 = reinterpret_cast<float4*>(&dst[(size_t)(row0 + r0 + 1) * DK_ + j0]);
    *o0 = make_float4(acc0[0], acc0[1], acc0[2], acc0[3]);
    *o1 = make_float4(acc1[0], acc1[1], acc1[2], acc1[3]);
}

// ---------------------------------------------------------------------------
// Kernel 2: fused  scores -> softmax -> write attn x4 -> attn@V -> @Wo
// grid = B * (T/R) = 1024 CTAs, block = 256 threads.
// Dynamic smem: scores[R*T] + kv[ST*65] + qh[R*DK] + rinv[R]
// ---------------------------------------------------------------------------
#define SMEM_FLOATS (R_ * T_ + ST_ * 65 + R_ * DK_ + R_)
#define SMEM_BYTES  (SMEM_FLOATS * 4)

__global__ void attn_kernel(const float* __restrict__ Wo,
                            float* __restrict__ out,
                            float* __restrict__ attn_out) {
    extern __shared__ float sm[];
    float* sc   = sm;                       // R*T   = 32768 floats (128 KB)
    float* kv   = sc + R_ * T_;             // 128*65 = 8320 floats
    float* qh   = kv + ST_ * 65;            // R*DK  = 1024 floats
    float* rinv = qh + R_ * DK_;            // R

    const int tid = threadIdx.x;
    const int b   = blockIdx.x >> 7;        // 128 row-tiles per batch
    const int t0  = (blockIdx.x & 127) * R_;

    // ---- load q tile into smem -------------------------------------------
    {
        const size_t qbase = ((size_t)b * T_ + t0) * DK_;
        for (int i = tid; i < R_ * DK_; i += TH_) qh[i] = g_qs[qbase + i];
    }
    __syncthreads();

    // ---- phase 1: scores = qs . ks^T * 0.125 ------------------------------
    {
        const int s_local = tid & 127;       // 128 s per tile
        const int rbase   = (tid >> 7) * 8;  // rows 0-7 or 8-15
        for (int st = 0; st < T_; st += ST_) {
            // load K tile with stride-65 padding (conflict-free lane-varies-s)
            const float* ksrc = g_ks + ((size_t)b * T_ + st) * DK_;
            for (int i = tid; i < ST_ * DK_; i += TH_) {
                int s = i >> 6, d = i & 63;
                kv[s * 65 + d] = ksrc[i];
            }
            __syncthreads();

            float acc[8] = {0.f, 0.f, 0.f, 0.f, 0.f, 0.f, 0.f, 0.f};
            #pragma unroll 4
            for (int d = 0; d < DK_; d += 4) {
                const float k0 = kv[s_local * 65 + d + 0];
                const float k1 = kv[s_local * 65 + d + 1];
                const float k2 = kv[s_local * 65 + d + 2];
                const float k3 = kv[s_local * 65 + d + 3];
                #pragma unroll
                for (int r = 0; r < 8; r++) {
                    float4 q4 = *reinterpret_cast<const float4*>(&qh[(rbase + r) * DK_ + d]);
                    acc[r] += q4.x * k0 + q4.y * k1 + q4.z * k2 + q4.w * k3;
                }
            }
            #pragma unroll
            for (int r = 0; r < 8; r++)
                sc[(rbase + r) * T_ + st + s_local] = acc[r] * 0.125f;
            __syncthreads();   // before kv reuse next iter
        }
    }

    // ---- phase 2: softmax (two-pass, per-row, 16 threads per row) ---------
    {
        const int r   = tid >> 4;
        const int l16 = tid & 15;
        float* row = sc + r * T_;

        float m = -1e30f;
        for (int s = l16; s < T_; s += 16) m = fmaxf(m, row[s]);
        #pragma unroll
        for (int o = 8; o > 0; o >>= 1)
            m = fmaxf(m, __shfl_xor_sync(0xffffffffu, m, o));

        float sum = 0.f;
        for (int s = l16; s < T_; s += 16) {
            float p = __expf(row[s] - m);
            row[s] = p;
            sum += p;
        }
        #pragma unroll
        for (int o = 8; o > 0; o >>= 1)
            sum += __shfl_xor_sync(0xffffffffu, sum, o);

        if (l16 == 0) rinv[r] = 1.0f / sum;
    }
    __syncthreads();

    // ---- phase 3: normalize in place + write attn to all 4 heads ----------
    {
        const size_t HTT   = (size_t)B_ * T_ * T_;           // 33,554,432
        const size_t abase = ((size_t)b * T_ + t0) * T_;
        float4* sc4 = reinterpret_cast<float4*>(sc);
        for (int i = tid; i < R_ * T_ / 4; i += TH_) {
            const int rr = i >> 9;                           // T/4 = 512 per row
            const int s4 = i & 511;
            const float inv = rinv[rr];
            float4 vv = sc4[i];
            vv.x *= inv; vv.y *= inv; vv.z *= inv; vv.w *= inv;
            sc4[i] = vv;
            const size_t off = abase + (size_t)rr * T_ + (size_t)s4 * 4;
            #pragma unroll
            for (int h = 0; h < NHEAD_; h++)
                *reinterpret_cast<float4*>(attn_out + (size_t)h * HTT + off) = vv;
        }
    }
    __syncthreads();

    // ---- phase 4: head = attn @ vs  (thread = 1 row x 4 cols) -------------
    float a0 = 0.f, a1 = 0.f, a2 = 0.f, a3 = 0.f;
    {
        const int d4 = (tid & 15) * 4;
        const int hr = tid >> 4;
        for (int st = 0; st < T_; st += ST_) {
            __syncthreads();   // kv reuse guard
            const float4* vsrc =
                reinterpret_cast<const float4*>(g_vs + ((size_t)b * T_ + st) * DK_);
            float4* kv4 = reinterpret_cast<float4*>(kv);
            for (int i = tid; i < ST_ * DK_ / 4; i += TH_) kv4[i] = vsrc[i];
            __syncthreads();

            const float* prow = sc + hr * T_ + st;
            #pragma unroll 8
            for (int sl = 0; sl < ST_; sl++) {
                const float p = prow[sl];
                float4 vv = *reinterpret_cast<const float4*>(&kv[sl * DK_ + d4]);
                a0 += p * vv.x; a1 += p * vv.y; a2 += p * vv.z; a3 += p * vv.w;
            }
        }
        __syncthreads();
        *reinterpret_cast<float4*>(&qh[hr * DK_ + d4]) = make_float4(a0, a1, a2, a3);
    }
    __syncthreads();

    // ---- phase 5: outputs = head @ Wo  (thread = column c, 16 rows) -------
    {
        const int c = tid;
        float o[R_];
        #pragma unroll
        for (int rr = 0; rr < R_; rr++) o[rr] = 0.f;

        for (int d = 0; d < DK_; d++) {
            const float w = Wo[(size_t)d * D_ + c];
            #pragma unroll
            for (int rr = 0; rr < R_; rr++) o[rr] += qh[rr * DK_ + d] * w;
        }
        const size_t obase = ((size_t)b * T_ + t0) * D_ + c;
        #pragma unroll
        for (int rr = 0; rr < R_; rr++) out[obase + (size_t)rr * D_] = o[rr];
    }
}

// ---------------------------------------------------------------------------
// launch
// ---------------------------------------------------------------------------
extern "C" void kernel_launch(void* const* d_in, const int* in_sizes, int n_in,
                              void* d_out, int out_size) {
    const float* q  = (const float*)d_in[0];
    const float* k  = (const float*)d_in[1];
    const float* v  = (const float*)d_in[2];
    const float* Wq = (const float*)d_in[3];
    const float* Wk = (const float*)d_in[4];
    const float* Wv = (const float*)d_in[5];
    const float* Wo = (const float*)d_in[6];

    float* out      = (float*)d_out;                               // [8,2048,256]
    float* attn_out = (float*)d_out + (size_t)B_ * T_ * D_;        // [4,8,2048,2048]

    // projections: 16384 rows / 32 per block = 512 blocks, y = {q,k,v}
    dim3 gp(512, 3, 1);
    proj_kernel<<<gp, TH_>>>(q, k, v, Wq, Wk, Wv);

    // fused attention
    cudaFuncSetAttribute(attn_kernel, cudaFuncAttributeMaxDynamicSharedMemorySize,
                         SMEM_BYTES);
    attn_kernel<<<B_ * (T_ / R_), TH_, SMEM_BYTES>>>(Wo, out, attn_out);
}

// round 4
// speedup vs baseline: 1.9811x; 1.9811x over previous
#include <cuda_runtime.h>
#include <cstddef>

// Problem constants
#define B_  8
#define T_  2048
#define D_  256
#define DK_ 64
#define NHEAD_ 4

// Fused attention kernel tiling
#define R_   16      // query rows per CTA
#define ST_  256     // key/value tile along s
#define TH_  512     // threads per CTA

// Scratch for projected q/k/v  (8*2048*64 fp32 = 4 MB each)
__device__ float g_qs[B_ * T_ * DK_];
__device__ float g_ks[B_ * T_ * DK_];
__device__ float g_vs[B_ * T_ * DK_];

// ---------------------------------------------------------------------------
// Kernel 1: projections  qs = q@Wq, ks = k@Wk, vs = v@Wv
// grid = (256, 3), block = 256.  Each block: 64 rows x 64 cols of one proj.
// W cached in smem; thread tile 4 rows x 4 cols (2.0 smem-B/MAC).
// ---------------------------------------------------------------------------
#define PROJ_TH 256
#define PROJ_ROWS 64
#define PROJ_SMEM ((PROJ_ROWS * 256 + 256 * DK_) * 4)   // xs 64KB + Ws 64KB

__global__ __launch_bounds__(PROJ_TH, 1)
void proj_kernel(const float* __restrict__ q,
                 const float* __restrict__ k,
                 const float* __restrict__ v,
                 const float* __restrict__ Wq,
                 const float* __restrict__ Wk,
                 const float* __restrict__ Wv) {
    extern __shared__ float psm[];
    float* xs = psm;                       // 64*256
    float* Ws = psm + PROJ_ROWS * 256;     // 256*64

    const float* x;
    const float* W;
    float* dst;
    if (blockIdx.y == 0)      { x = q; W = Wq; dst = g_qs; }
    else if (blockIdx.y == 1) { x = k; W = Wk; dst = g_ks; }
    else                      { x = v; W = Wv; dst = g_vs; }

    const int row0 = blockIdx.x * PROJ_ROWS;
    const int tid  = threadIdx.x;

    // load 64 input rows + full W as float4
    {
        const float4* src4 = reinterpret_cast<const float4*>(x + (size_t)row0 * D_);
        float4* xs4 = reinterpret_cast<float4*>(xs);
        #pragma unroll
        for (int i = tid; i < PROJ_ROWS * 256 / 4; i += PROJ_TH) xs4[i] = src4[i];
        const float4* w4 = reinterpret_cast<const float4*>(W);
        float4* ws4 = reinterpret_cast<float4*>(Ws);
        #pragma unroll
        for (int i = tid; i < 256 * DK_ / 4; i += PROJ_TH) ws4[i] = w4[i];
    }
    __syncthreads();

    // thread tile: 4 rows x 4 cols.  16 col groups x 16 row groups = 256 thr
    const int jg = tid & 15;
    const int rg = tid >> 4;
    const int j0 = jg * 4;
    const int r0 = rg * 4;

    float acc[4][4];
    #pragma unroll
    for (int r = 0; r < 4; r++)
        #pragma unroll
        for (int c = 0; c < 4; c++) acc[r][c] = 0.f;

    for (int i = 0; i < D_; i += 4) {
        float4 xr[4];
        #pragma unroll
        for (int r = 0; r < 4; r++)
            xr[r] = *reinterpret_cast<const float4*>(&xs[(r0 + r) * 256 + i]);
        #pragma unroll
        for (int ii = 0; ii < 4; ii++) {
            float4 w = *reinterpret_cast<const float4*>(&Ws[(i + ii) * DK_ + j0]);
            #pragma unroll
            for (int r = 0; r < 4; r++) {
                const float xv = (ii == 0) ? xr[r].x : (ii == 1) ? xr[r].y
                                : (ii == 2) ? xr[r].z : xr[r].w;
                acc[r][0] += xv * w.x; acc[r][1] += xv * w.y;
                acc[r][2] += xv * w.z; acc[r][3] += xv * w.w;
            }
        }
    }

    #pragma unroll
    for (int r = 0; r < 4; r++) {
        float4* o = reinterpret_cast<float4*>(&dst[(size_t)(row0 + r0 + r) * DK_ + j0]);
        *o = make_float4(acc[r][0], acc[r][1], acc[r][2], acc[r][3]);
    }
}

// ---------------------------------------------------------------------------
// Kernel 2: fused  scores -> softmax -> write attn x4 -> attn@V -> @Wo
// grid = B * (T/R) = 1024 CTAs, block = 512 threads.
// smem: sc[16*2048] + kv[256*68] + qh[16*64] + red[256*17] + rinv[16]
// ---------------------------------------------------------------------------
#define KPAD 68
#define SMEM_FLOATS (R_ * T_ + ST_ * KPAD + R_ * DK_ + 256 * 17 + 16)
#define SMEM_BYTES  (SMEM_FLOATS * 4)

__global__ __launch_bounds__(TH_, 1)
void attn_kernel(const float* __restrict__ Wo,
                 float* __restrict__ out,
                 float* __restrict__ attn_out) {
    extern __shared__ float sm[];
    float* sc   = sm;                        // 32768 floats (128 KB)
    float* kv   = sc + R_ * T_;              // 256*68 = 17408 floats
    float* qh   = kv + ST_ * KPAD;           // 1024 floats
    float* red  = qh + R_ * DK_;             // 256*17 = 4352 floats
    float* rinv = red + 256 * 17;            // 16

    const int tid = threadIdx.x;
    const int b   = blockIdx.x >> 7;
    const int t0  = (blockIdx.x & 127) * R_;

    // ---- load q tile --------------------------------------------------------
    {
        const size_t qbase = ((size_t)b * T_ + t0) * DK_;
        for (int i = tid; i < R_ * DK_; i += TH_) qh[i] = g_qs[qbase + i];
    }
    __syncthreads();

    // ---- phase 1: scores = qs . ks^T * 0.125 --------------------------------
    // thread tile 4r x 4s, d split in 2 halves across the two thread-halves.
    {
        const int sg = tid & 63;            // 64 s groups (s = sg + 64*si)
        const int rg = (tid >> 6) & 3;      // 4 row groups (4 rows each)
        const int dh = tid >> 8;            // d half: 0 -> d[0,32), 1 -> d[32,64)
        const int d0 = dh * 32;

        for (int st = 0; st < T_; st += ST_) {
            // fill K tile, stride KPAD (=68) so lane-varies-s LDS.128 is
            // conflict-free (stride 272B -> 8 lanes span banks 0,4,...,28)
            const float4* ksrc4 =
                reinterpret_cast<const float4*>(g_ks + ((size_t)b * T_ + st) * DK_);
            for (int i = tid; i < ST_ * 16; i += TH_) {
                const int s = i >> 4, dq = i & 15;
                *reinterpret_cast<float4*>(&kv[s * KPAD + dq * 4]) = ksrc4[i];
            }
            __syncthreads();

            float acc[4][4];
            #pragma unroll
            for (int r = 0; r < 4; r++)
                #pragma unroll
                for (int si = 0; si < 4; si++) acc[r][si] = 0.f;

            #pragma unroll
            for (int dd = 0; dd < 32; dd += 4) {
                const int d = d0 + dd;
                float4 q4[4];
                #pragma unroll
                for (int r = 0; r < 4; r++)
                    q4[r] = *reinterpret_cast<const float4*>(&qh[(rg * 4 + r) * DK_ + d]);
                #pragma unroll
                for (int si = 0; si < 4; si++) {
                    const int s = sg + 64 * si;
                    float4 kk = *reinterpret_cast<const float4*>(&kv[s * KPAD + d]);
                    #pragma unroll
                    for (int r = 0; r < 4; r++)
                        acc[r][si] += q4[r].x * kk.x + q4[r].y * kk.y
                                    + q4[r].z * kk.z + q4[r].w * kk.w;
                }
            }

            if (dh == 1) {
                #pragma unroll
                for (int r = 0; r < 4; r++)
                    #pragma unroll
                    for (int si = 0; si < 4; si++)
                        red[(tid - 256) * 17 + r * 4 + si] = acc[r][si];
            }
            __syncthreads();
            if (dh == 0) {
                #pragma unroll
                for (int r = 0; r < 4; r++)
                    #pragma unroll
                    for (int si = 0; si < 4; si++) {
                        const float val = acc[r][si] + red[tid * 17 + r * 4 + si];
                        sc[(rg * 4 + r) * T_ + st + sg + 64 * si] = val * 0.125f;
                    }
            }
            __syncthreads();
        }
    }

    // ---- phase 2: softmax (one warp per row) --------------------------------
    {
        const int w    = tid >> 5;          // 16 rows
        const int lane = tid & 31;
        float* row = sc + w * T_;

        float m = -1e30f;
        for (int s = lane; s < T_; s += 32) m = fmaxf(m, row[s]);
        #pragma unroll
        for (int o = 16; o > 0; o >>= 1)
            m = fmaxf(m, __shfl_xor_sync(0xffffffffu, m, o));

        float sum = 0.f;
        for (int s = lane; s < T_; s += 32) {
            const float p = __expf(row[s] - m);
            row[s] = p;
            sum += p;
        }
        #pragma unroll
        for (int o = 16; o > 0; o >>= 1)
            sum += __shfl_xor_sync(0xffffffffu, sum, o);

        if (lane == 0) rinv[w] = 1.0f / sum;
    }
    __syncthreads();

    // ---- phase 3: normalize in place + write attn to all 4 heads ------------
    {
        const size_t HTT   = (size_t)B_ * T_ * T_;
        const size_t abase = ((size_t)b * T_ + t0) * T_;
        float4* sc4 = reinterpret_cast<float4*>(sc);
        for (int i = tid; i < R_ * T_ / 4; i += TH_) {
            const int rr = i >> 9;
            const int s4 = i & 511;
            const float inv = rinv[rr];
            float4 vv = sc4[i];
            vv.x *= inv; vv.y *= inv; vv.z *= inv; vv.w *= inv;
            sc4[i] = vv;
            const size_t off = abase + (size_t)rr * T_ + (size_t)s4 * 4;
            #pragma unroll
            for (int h = 0; h < NHEAD_; h++)
                *reinterpret_cast<float4*>(attn_out + (size_t)h * HTT + off) = vv;
        }
    }
    __syncthreads();

    // ---- phase 4: head = attn @ vs  (thread tile 4r x 4d, s split 8 ways) ---
    {
        const int dg  = tid & 15;           // 16 d groups (4 d each)
        const int rg4 = (tid >> 4) & 3;     // 4 row groups (4 rows each)
        const int ss  = tid >> 6;           // 8 s subgroups (32 s each per tile)
        const int d4  = dg * 4;

        float acc[4][4];
        #pragma unroll
        for (int r = 0; r < 4; r++)
            #pragma unroll
            for (int c = 0; c < 4; c++) acc[r][c] = 0.f;

        for (int st = 0; st < T_; st += ST_) {
            __syncthreads();                // kv reuse guard
            const float4* vsrc4 =
                reinterpret_cast<const float4*>(g_vs + ((size_t)b * T_ + st) * DK_);
            float4* kv4 = reinterpret_cast<float4*>(kv);
            for (int i = tid; i < ST_ * DK_ / 4; i += TH_) kv4[i] = vsrc4[i];
            __syncthreads();

            const int sbase = ss * 32;
            #pragma unroll 4
            for (int j = 0; j < 32; j++) {
                const int sl = sbase + j;
                float p[4];
                #pragma unroll
                for (int r = 0; r < 4; r++)
                    p[r] = sc[(rg4 * 4 + r) * T_ + st + sl];
                float4 vv = *reinterpret_cast<const float4*>(&kv[sl * DK_ + d4]);
                #pragma unroll
                for (int r = 0; r < 4; r++) {
                    acc[r][0] += p[r] * vv.x; acc[r][1] += p[r] * vv.y;
                    acc[r][2] += p[r] * vv.z; acc[r][3] += p[r] * vv.w;
                }
            }
        }
        __syncthreads();

        // reduce over the 8 s-subgroups via smem (reuse kv, stride 17)
        #pragma unroll
        for (int r = 0; r < 4; r++)
            #pragma unroll
            for (int c = 0; c < 4; c++)
                kv[tid * 17 + r * 4 + c] = acc[r][c];
        __syncthreads();

        for (int item = tid; item < 64 * 16; item += TH_) {
            const int pos = item >> 4;      // (rg<<4)|dg
            const int i   = item & 15;      // (r<<2)|c
            float s = 0.f;
            #pragma unroll
            for (int j = 0; j < 8; j++) s += kv[(pos + 64 * j) * 17 + i];
            const int prg = pos >> 4, pdg = pos & 15;
            const int r = i >> 2, c = i & 3;
            qh[(prg * 4 + r) * DK_ + pdg * 4 + c] = s;
        }
    }
    __syncthreads();

    // ---- phase 5: outputs = head @ Wo  (thread = column, 8 rows) ------------
    {
        const int c  = tid & 255;
        const int rh = tid >> 8;            // 2 row halves of 8
        float o[8];
        #pragma unroll
        for (int rr = 0; rr < 8; rr++) o[rr] = 0.f;

        for (int d = 0; d < DK_; d++) {
            const float w = Wo[(size_t)d * D_ + c];
            #pragma unroll
            for (int rr = 0; rr < 8; rr++)
                o[rr] += qh[(rh * 8 + rr) * DK_ + d] * w;
        }
        const size_t obase = ((size_t)b * T_ + t0 + rh * 8) * D_ + c;
        #pragma unroll
        for (int rr = 0; rr < 8; rr++) out[obase + (size_t)rr * D_] = o[rr];
    }
}

// ---------------------------------------------------------------------------
// launch
// ---------------------------------------------------------------------------
extern "C" void kernel_launch(void* const* d_in, const int* in_sizes, int n_in,
                              void* d_out, int out_size) {
    const float* q  = (const float*)d_in[0];
    const float* k  = (const float*)d_in[1];
    const float* v  = (const float*)d_in[2];
    const float* Wq = (const float*)d_in[3];
    const float* Wk = (const float*)d_in[4];
    const float* Wv = (const float*)d_in[5];
    const float* Wo = (const float*)d_in[6];

    float* out      = (float*)d_out;                               // [8,2048,256]
    float* attn_out = (float*)d_out + (size_t)B_ * T_ * D_;        // [4,8,2048,2048]

    // projections: 16384 rows / 64 per block, y = {q,k,v}
    cudaFuncSetAttribute(proj_kernel, cudaFuncAttributeMaxDynamicSharedMemorySize,
                         PROJ_SMEM);
    dim3 gp(16384 / PROJ_ROWS, 3, 1);
    proj_kernel<<<gp, PROJ_TH, PROJ_SMEM>>>(q, k, v, Wq, Wk, Wv);

    // fused attention
    cudaFuncSetAttribute(attn_kernel, cudaFuncAttributeMaxDynamicSharedMemorySize,
                         SMEM_BYTES);
    attn_kernel<<<B_ * (T_ / R_), TH_, SMEM_BYTES>>>(Wo, out, attn_out);
}

// round 5
// speedup vs baseline: 2.0599x; 1.0398x over previous
#include <cuda_runtime.h>
#include <cstddef>

// Problem constants
#define B_  8
#define T_  2048
#define D_  256
#define DK_ 64
#define NHEAD_ 4

// Fused attention kernel tiling
#define R_   16      // query rows per CTA
#define ST_  256     // key/value tile along s
#define TH_  512     // threads per CTA

// Scratch for projected q/k/v  (8*2048*64 fp32 = 4 MB each)
__device__ float g_qs[B_ * T_ * DK_];
__device__ float g_ks[B_ * T_ * DK_];
__device__ float g_vs[B_ * T_ * DK_];

// ---- packed f32x2 helpers (SASS FFMA2 — PTX-only pattern) ------------------
__device__ __forceinline__ void ffma2(unsigned long long& acc,
                                      unsigned long long a,
                                      unsigned long long b) {
    asm("fma.rn.f32x2 %0, %1, %2, %0;" : "+l"(acc) : "l"(a), "l"(b));
}
__device__ __forceinline__ unsigned long long pack2(float lo, float hi) {
    unsigned long long r;
    asm("mov.b64 %0, {%1, %2};" : "=l"(r) : "f"(lo), "f"(hi));
    return r;
}
__device__ __forceinline__ float pairsum(unsigned long long p) {
    float lo, hi;
    asm("mov.b64 {%0, %1}, %2;" : "=f"(lo), "=f"(hi) : "l"(p));
    return lo + hi;
}
__device__ __forceinline__ void unpack2(float& lo, float& hi, unsigned long long p) {
    asm("mov.b64 {%0, %1}, %2;" : "=f"(lo), "=f"(hi) : "l"(p));
}

// ---------------------------------------------------------------------------
// Kernel 1: projections  qs = q@Wq, ks = k@Wk, vs = v@Wv
// grid = (256, 3), block = 256.  Each block: 64 rows x 64 cols of one proj.
// ---------------------------------------------------------------------------
#define PROJ_TH 256
#define PROJ_ROWS 64
#define PROJ_SMEM ((PROJ_ROWS * 256 + 256 * DK_) * 4)   // xs 64KB + Ws 64KB

__global__ __launch_bounds__(PROJ_TH, 1)
void proj_kernel(const float* __restrict__ q,
                 const float* __restrict__ k,
                 const float* __restrict__ v,
                 const float* __restrict__ Wq,
                 const float* __restrict__ Wk,
                 const float* __restrict__ Wv) {
    extern __shared__ float psm[];
    float* xs = psm;                       // 64*256
    float* Ws = psm + PROJ_ROWS * 256;     // 256*64

    const float* x;
    const float* W;
    float* dst;
    if (blockIdx.y == 0)      { x = q; W = Wq; dst = g_qs; }
    else if (blockIdx.y == 1) { x = k; W = Wk; dst = g_ks; }
    else                      { x = v; W = Wv; dst = g_vs; }

    const int row0 = blockIdx.x * PROJ_ROWS;
    const int tid  = threadIdx.x;

    {
        const float4* src4 = reinterpret_cast<const float4*>(x + (size_t)row0 * D_);
        float4* xs4 = reinterpret_cast<float4*>(xs);
        #pragma unroll
        for (int i = tid; i < PROJ_ROWS * 256 / 4; i += PROJ_TH) xs4[i] = src4[i];
        const float4* w4 = reinterpret_cast<const float4*>(W);
        float4* ws4 = reinterpret_cast<float4*>(Ws);
        #pragma unroll
        for (int i = tid; i < 256 * DK_ / 4; i += PROJ_TH) ws4[i] = w4[i];
    }
    __syncthreads();

    // thread tile: 4 rows x 4 cols, inner math in f32x2 pairs over columns
    const int jg = tid & 15;
    const int rg = tid >> 4;
    const int j0 = jg * 4;
    const int r0 = rg * 4;

    unsigned long long acc2[4][2];
    #pragma unroll
    for (int r = 0; r < 4; r++) { acc2[r][0] = 0ULL; acc2[r][1] = 0ULL; }

    for (int i = 0; i < D_; i += 4) {
        float4 xr[4];
        #pragma unroll
        for (int r = 0; r < 4; r++)
            xr[r] = *reinterpret_cast<const float4*>(&xs[(r0 + r) * 256 + i]);
        #pragma unroll
        for (int ii = 0; ii < 4; ii++) {
            ulonglong2 w2 = *reinterpret_cast<const ulonglong2*>(&Ws[(i + ii) * DK_ + j0]);
            #pragma unroll
            for (int r = 0; r < 4; r++) {
                const float xv = (ii == 0) ? xr[r].x : (ii == 1) ? xr[r].y
                                : (ii == 2) ? xr[r].z : xr[r].w;
                const unsigned long long x2 = pack2(xv, xv);
                ffma2(acc2[r][0], x2, w2.x);
                ffma2(acc2[r][1], x2, w2.y);
            }
        }
    }

    #pragma unroll
    for (int r = 0; r < 4; r++) {
        float a0, a1, a2, a3;
        unpack2(a0, a1, acc2[r][0]);
        unpack2(a2, a3, acc2[r][1]);
        float4* o = reinterpret_cast<float4*>(&dst[(size_t)(row0 + r0 + r) * DK_ + j0]);
        *o = make_float4(a0, a1, a2, a3);
    }
}

// ---------------------------------------------------------------------------
// Kernel 2: fused  scores -> softmax -> write attn x4 -> attn@V -> @Wo
// grid = B * (T/R) = 1024 CTAs, block = 512 threads.
// smem: sc[16*2048] + kv[256*68] + qh[16*64] + rinv[16]   (~200 KB)
// ---------------------------------------------------------------------------
#define KPAD 68
#define SMEM_FLOATS (R_ * T_ + ST_ * KPAD + R_ * DK_ + 16)
#define SMEM_BYTES  (SMEM_FLOATS * 4)

__global__ __launch_bounds__(TH_, 1)
void attn_kernel(const float* __restrict__ Wo,
                 float* __restrict__ out,
                 float* __restrict__ attn_out) {
    extern __shared__ float sm[];
    float* sc   = sm;                        // 32768 floats (128 KB)
    float* kv   = sc + R_ * T_;              // 256*68 = 17408 floats
    float* qh   = kv + ST_ * KPAD;           // 1024 floats
    float* rinv = qh + R_ * DK_;             // 16

    const int tid = threadIdx.x;
    const int b   = blockIdx.x >> 7;
    const int t0  = (blockIdx.x & 127) * R_;

    // ---- load q tile --------------------------------------------------------
    {
        const size_t qbase = ((size_t)b * T_ + t0) * DK_;
        for (int i = tid; i < R_ * DK_; i += TH_) qh[i] = g_qs[qbase + i];
    }
    __syncthreads();

    // ---- phase 1: scores = qs . ks^T * 0.125 --------------------------------
    // thread tile 4r x 4s over 32 d; d-half partner = same warp (lane xor 8),
    // reduced with shfl (no smem round-trip).  Math in f32x2 pairs.
    {
        const int dh = (tid >> 3) & 1;                 // d half (lane bit 3)
        const int sg = (tid & 7) | ((tid >> 1) & 56);  // 64 s groups
        const int rg = tid >> 7;                       // 4 row groups
        const int d0 = dh * 32;

        for (int st = 0; st < T_; st += ST_) {
            // fill K tile, stride KPAD (=68): lane-varies-s LDS.128 conflict-free
            const float4* ksrc4 =
                reinterpret_cast<const float4*>(g_ks + ((size_t)b * T_ + st) * DK_);
            for (int i = tid; i < ST_ * 16; i += TH_) {
                const int s = i >> 4, dq = i & 15;
                *reinterpret_cast<float4*>(&kv[s * KPAD + dq * 4]) = ksrc4[i];
            }
            __syncthreads();

            unsigned long long acc2[4][4];
            #pragma unroll
            for (int r = 0; r < 4; r++)
                #pragma unroll
                for (int si = 0; si < 4; si++) acc2[r][si] = 0ULL;

            #pragma unroll
            for (int dd = 0; dd < 32; dd += 4) {
                const int d = d0 + dd;
                ulonglong2 q2[4];
                #pragma unroll
                for (int r = 0; r < 4; r++)
                    q2[r] = *reinterpret_cast<const ulonglong2*>(
                        &qh[(rg * 4 + r) * DK_ + d]);
                #pragma unroll
                for (int si = 0; si < 4; si++) {
                    const int s = sg + 64 * si;
                    ulonglong2 k2 = *reinterpret_cast<const ulonglong2*>(
                        &kv[s * KPAD + d]);
                    #pragma unroll
                    for (int r = 0; r < 4; r++) {
                        ffma2(acc2[r][si], q2[r].x, k2.x);
                        ffma2(acc2[r][si], q2[r].y, k2.y);
                    }
                }
            }

            // pair-lane reduction + store (each d-half writes 2 of 4 si's)
            #pragma unroll
            for (int r = 0; r < 4; r++)
                #pragma unroll
                for (int si = 0; si < 4; si++) {
                    float v = pairsum(acc2[r][si]);
                    v += __shfl_xor_sync(0xffffffffu, v, 8);
                    if ((si >> 1) == dh)
                        sc[(rg * 4 + r) * T_ + st + sg + 64 * si] = v * 0.125f;
                }
            __syncthreads();
        }
    }

    // ---- phase 2: softmax (one warp per row) --------------------------------
    {
        const int w    = tid >> 5;
        const int lane = tid & 31;
        float* row = sc + w * T_;

        float m = -1e30f;
        for (int s = lane; s < T_; s += 32) m = fmaxf(m, row[s]);
        #pragma unroll
        for (int o = 16; o > 0; o >>= 1)
            m = fmaxf(m, __shfl_xor_sync(0xffffffffu, m, o));

        float sum = 0.f;
        for (int s = lane; s < T_; s += 32) {
            const float p = __expf(row[s] - m);
            row[s] = p;
            sum += p;
        }
        #pragma unroll
        for (int o = 16; o > 0; o >>= 1)
            sum += __shfl_xor_sync(0xffffffffu, sum, o);

        if (lane == 0) rinv[w] = 1.0f / sum;
    }
    __syncthreads();

    // ---- phase 3: normalize in place + write attn to all 4 heads ------------
    {
        const size_t HTT   = (size_t)B_ * T_ * T_;
        const size_t abase = ((size_t)b * T_ + t0) * T_;
        float4* sc4 = reinterpret_cast<float4*>(sc);
        for (int i = tid; i < R_ * T_ / 4; i += TH_) {
            const int rr = i >> 9;
            const int s4 = i & 511;
            const float inv = rinv[rr];
            float4 vv = sc4[i];
            vv.x *= inv; vv.y *= inv; vv.z *= inv; vv.w *= inv;
            sc4[i] = vv;
            const size_t off = abase + (size_t)rr * T_ + (size_t)s4 * 4;
            #pragma unroll
            for (int h = 0; h < NHEAD_; h++)
                *reinterpret_cast<float4*>(attn_out + (size_t)h * HTT + off) = vv;
        }
    }
    __syncthreads();

    // ---- phase 4: head = attn @ vs  (tile 4r x 4d, s split 8 ways, f32x2) ---
    {
        const int dg  = tid & 15;           // 16 d groups (4 d each)
        const int rg4 = (tid >> 4) & 3;     // 4 row groups (4 rows each)
        const int ss  = tid >> 6;           // 8 s subgroups (32 s each per tile)
        const int d4  = dg * 4;

        unsigned long long acc2[4][2];
        #pragma unroll
        for (int r = 0; r < 4; r++) { acc2[r][0] = 0ULL; acc2[r][1] = 0ULL; }

        for (int st = 0; st < T_; st += ST_) {
            __syncthreads();                // kv reuse guard
            const float4* vsrc4 =
                reinterpret_cast<const float4*>(g_vs + ((size_t)b * T_ + st) * DK_);
            float4* kv4 = reinterpret_cast<float4*>(kv);
            for (int i = tid; i < ST_ * DK_ / 4; i += TH_) kv4[i] = vsrc4[i];
            __syncthreads();

            const int sbase = ss * 32;
            #pragma unroll 4
            for (int j = 0; j < 32; j++) {
                const int sl = sbase + j;
                ulonglong2 v2 = *reinterpret_cast<const ulonglong2*>(
                    &kv[sl * DK_ + d4]);
                #pragma unroll
                for (int r = 0; r < 4; r++) {
                    const float p = sc[(rg4 * 4 + r) * T_ + st + sl];
                    const unsigned long long p2 = pack2(p, p);
                    ffma2(acc2[r][0], p2, v2.x);
                    ffma2(acc2[r][1], p2, v2.y);
                }
            }
        }
        __syncthreads();

        // reduce over the 8 s-subgroups via smem (reuse kv, stride 17)
        #pragma unroll
        for (int r = 0; r < 4; r++) {
            float a0, a1, a2, a3;
            unpack2(a0, a1, acc2[r][0]);
            unpack2(a2, a3, acc2[r][1]);
            kv[tid * 17 + r * 4 + 0] = a0;
            kv[tid * 17 + r * 4 + 1] = a1;
            kv[tid * 17 + r * 4 + 2] = a2;
            kv[tid * 17 + r * 4 + 3] = a3;
        }
        __syncthreads();

        for (int item = tid; item < 64 * 16; item += TH_) {
            const int pos = item >> 4;      // (rg<<4)|dg
            const int i   = item & 15;      // (r<<2)|c
            float s = 0.f;
            #pragma unroll
            for (int j = 0; j < 8; j++) s += kv[(pos + 64 * j) * 17 + i];
            const int prg = pos >> 4, pdg = pos & 15;
            const int r = i >> 2, c = i & 3;
            qh[(prg * 4 + r) * DK_ + pdg * 4 + c] = s;
        }
    }
    __syncthreads();

    // ---- phase 5: outputs = head @ Wo  (thread = column, 8 rows) ------------
    {
        const int c  = tid & 255;
        const int rh = tid >> 8;
        float o[8];
        #pragma unroll
        for (int rr = 0; rr < 8; rr++) o[rr] = 0.f;

        for (int d = 0; d < DK_; d++) {
            const float w = Wo[(size_t)d * D_ + c];
            #pragma unroll
            for (int rr = 0; rr < 8; rr++)
                o[rr] += qh[(rh * 8 + rr) * DK_ + d] * w;
        }
        const size_t obase = ((size_t)b * T_ + t0 + rh * 8) * D_ + c;
        #pragma unroll
        for (int rr = 0; rr < 8; rr++) out[obase + (size_t)rr * D_] = o[rr];
    }
}

// ---------------------------------------------------------------------------
// launch
// ---------------------------------------------------------------------------
extern "C" void kernel_launch(void* const* d_in, const int* in_sizes, int n_in,
                              void* d_out, int out_size) {
    const float* q  = (const float*)d_in[0];
    const float* k  = (const float*)d_in[1];
    const float* v  = (const float*)d_in[2];
    const float* Wq = (const float*)d_in[3];
    const float* Wk = (const float*)d_in[4];
    const float* Wv = (const float*)d_in[5];
    const float* Wo = (const float*)d_in[6];

    float* out      = (float*)d_out;                               // [8,2048,256]
    float* attn_out = (float*)d_out + (size_t)B_ * T_ * D_;        // [4,8,2048,2048]

    cudaFuncSetAttribute(proj_kernel, cudaFuncAttributeMaxDynamicSharedMemorySize,
                         PROJ_SMEM);
    dim3 gp(16384 / PROJ_ROWS, 3, 1);
    proj_kernel<<<gp, PROJ_TH, PROJ_SMEM>>>(q, k, v, Wq, Wk, Wv);

    cudaFuncSetAttribute(attn_kernel, cudaFuncAttributeMaxDynamicSharedMemorySize,
                         SMEM_BYTES);
    attn_kernel<<<B_ * (T_ / R_), TH_, SMEM_BYTES>>>(Wo, out, attn_out);
}